// round 9
// baseline (speedup 1.0000x reference)
#include <cuda_runtime.h>
#include <math.h>

#define B_    32
#define N_    51
#define F_    4
#define P_    137
#define E_    408
#define NE_   (E_ + N_)      // 459 edges incl self-loops
#define EMB_  32
#define NF_   (N_ * F_)      // 204
#define ROW_  (N_ * EMB_)    // 1632
#define CH_   18             // P chunks (balanced 7/8)
#define PCM_  8              // max p per chunk
#define PAD_  (PCM_ + 1)     // 9

// Static device scratch
__device__ float g_part[(size_t)CH_ * B_ * ROW_];   // 4.2 MB partial accumulators
__device__ int   g_count[B_];                        // zero-init; reset each replay

__device__ __forceinline__ float htanh(float x) {
    float r;
    asm("tanh.approx.f32 %0, %1;" : "=f"(r) : "f"(x));
    return r;
}

// ---------------------------------------------------------------------------
// Single fused kernel. Block = (b, p-chunk of 7-8). Per-block parallel setup,
// warp-private aggregation + transform, last block per b runs the MLP head.
// ---------------------------------------------------------------------------
__global__ __launch_bounds__(256, 4) void main_kernel(
    const float* __restrict__ x,   const int* __restrict__ ei,
    const float* __restrict__ czw, const float* __restrict__ czb,
    const float* __restrict__ chw, const float* __restrict__ chb,
    const float* __restrict__ lzw, const float* __restrict__ lzb,
    const float* __restrict__ lhw, const float* __restrict__ lhb,
    const float* __restrict__ att,
    const float* __restrict__ l1w, const float* __restrict__ l1b,
    const float* __restrict__ l2w, const float* __restrict__ l2b,
    const float* __restrict__ l3w, const float* __restrict__ l3b,
    float* __restrict__ out)
{
    __shared__ float4 xt4  [N_ * PAD_];   // [n][p] over 4 f-channels
    __shared__ float4 aggs4[N_ * PAD_];
    __shared__ int    s_src[E_], s_dst[E_];
    __shared__ int2   s_edge[NE_];        // {src, nrm bits}
    __shared__ int    s_deg[N_], s_cnt[N_];
    __shared__ float  s_dinv[N_];
    __shared__ int    s_rp[N_ + 1];
    __shared__ float  s_wz[F_ * EMB_], s_wh[F_ * EMB_];
    __shared__ float  s_bz[EMB_], s_bh[EMB_];
    __shared__ float  s_probs[PCM_];      // pre-scaled by 0.5
    __shared__ float  s_ssum[N_ + 1];
    __shared__ int    s_last;

    const int tid = threadIdx.x, lane = tid & 31, w = tid >> 5;
    const int c  = blockIdx.x % CH_;
    const int b  = blockIdx.x / CH_;
    const int p0 = (c * P_) / CH_;
    const int pc = ((c + 1) * P_) / CH_ - p0;   // 7 or 8

    // ---- P0: edges, x tile, composed weights (all independent) ----
    if (tid < N_) s_deg[tid] = 0;
    for (int i = tid; i < E_; i += 256) { s_src[i] = ei[i]; s_dst[i] = ei[E_ + i]; }

    // x tile: i -> (row r = i>>3, p = i&7); xt4[n][p].f
    const float* xb = x + (size_t)b * NF_ * P_ + p0;
    for (int i = tid; i < NF_ * PCM_; i += 256) {
        int r = i >> 3, p = i & 7;
        if (p < pc) {
            int n = r >> 2, f = r & 3;
            ((float*)&xt4[n * PAD_ + p])[f] = xb[r * P_ + p];
        }
    }

    // composed weights: wz' = 0.5*(czw@lzw) (tanh half-arg), wh' = chw@lhw
    if (tid < 128) {
        int f = tid >> 5, e = tid & 31;
        float a = 0.f;
        #pragma unroll
        for (int k = 0; k < EMB_; k++) a += czw[f * EMB_ + k] * lzw[k * EMB_ + e];
        s_wz[tid] = a * 0.5f;
        if (f == 0) {
            float bb = lzb[e];
            #pragma unroll
            for (int k = 0; k < EMB_; k++) bb += czb[k] * lzw[k * EMB_ + e];
            s_bz[e] = bb * 0.5f;
        }
    } else {
        int t = tid - 128, f = t >> 5, e = t & 31;
        float a = 0.f;
        #pragma unroll
        for (int k = 0; k < EMB_; k++) a += chw[f * EMB_ + k] * lhw[k * EMB_ + e];
        s_wh[t] = a;
        if (f == 0) {
            float bb = lhb[e];
            #pragma unroll
            for (int k = 0; k < EMB_; k++) bb += chb[k] * lhw[k * EMB_ + e];
            s_bh[e] = bb;
        }
    }
    __syncthreads();

    // ---- P1: degrees (int smem atomics -> deterministic) ----
    for (int e = tid; e < E_; e += 256) atomicAdd(&s_deg[s_dst[e]], 1);
    __syncthreads();

    // ---- P2: scan (warp 0) | softmax (warp 1) | dinv | zero counters ----
    if (w == 0) {
        int v = (lane < N_) ? s_deg[lane] + 1 : 0;
        #pragma unroll
        for (int o = 1; o < 32; o <<= 1) {
            int t = __shfl_up_sync(0xffffffffu, v, o);
            if (lane >= o) v += t;
        }
        int base = __shfl_sync(0xffffffffu, v, 31);
        int v2 = (lane < N_ - 32) ? s_deg[32 + lane] + 1 : 0;
        #pragma unroll
        for (int o = 1; o < 32; o <<= 1) {
            int t = __shfl_up_sync(0xffffffffu, v2, o);
            if (lane >= o) v2 += t;
        }
        if (lane == 0) s_rp[0] = 0;
        s_rp[lane + 1] = v;
        if (lane < N_ - 32) s_rp[33 + lane] = base + v2;
    } else if (w == 1) {
        float mx = -1e30f;
        for (int p = lane; p < P_; p += 32) mx = fmaxf(mx, att[p]);
        #pragma unroll
        for (int o = 16; o; o >>= 1) mx = fmaxf(mx, __shfl_xor_sync(0xffffffffu, mx, o));
        float s = 0.f;
        for (int p = lane; p < P_; p += 32) s += __expf(att[p] - mx);
        #pragma unroll
        for (int o = 16; o; o >>= 1) s += __shfl_xor_sync(0xffffffffu, s, o);
        float inv = 0.5f / s;                 // fold the 0.5 gate factor here
        if (lane < pc) s_probs[lane] = __expf(att[p0 + lane] - mx) * inv;
    } else if (tid >= 64 && tid < 64 + N_) {
        s_dinv[tid - 64] = rsqrtf((float)(s_deg[tid - 64] + 1));
    } else if (tid >= 128 && tid < 128 + N_) {
        s_cnt[tid - 128] = 0;
    }
    __syncthreads();

    // ---- P3: CSR fill, stable order via match_any tiles (warp 0) ----
    if (w == 0) {
        #pragma unroll 1
        for (int t = 0; t < (E_ + 31) / 32; t++) {
            int e = t * 32 + lane;
            bool valid = e < E_;
            int d = valid ? s_dst[e] : -1;
            unsigned grp = __match_any_sync(0xffffffffu, d);
            int within = __popc(grp & ((1u << lane) - 1u));
            int lead   = __ffs(grp) - 1;
            int base = 0;
            if (valid) {
                base = s_cnt[d];
                int pos = s_rp[d] + base + within;
                int s   = s_src[e];
                s_edge[pos] = make_int2(s, __float_as_int(s_dinv[s] * s_dinv[d]));
            }
            __syncwarp();
            if (valid && lane == lead) s_cnt[d] = base + __popc(grp);
            __syncwarp();
        }
    } else if (tid >= 32 && tid < 32 + N_) {
        int n = tid - 32;
        int pos = s_rp[n + 1] - 1;        // self loop in last slot
        float dn = s_dinv[n];
        s_edge[pos] = make_int2(n, __float_as_int(dn * dn));
    }
    __syncthreads();

    // ---- P4: WARP-PRIVATE aggregation: warp w handles nodes w, w+8, ... ----
    for (int i = lane; i < 7 * PCM_; i += 32) {
        int nl = i >> 3, p = i & 7;
        int n = w + 8 * nl;
        if (n < N_ && p < pc) {
            float4 a = make_float4(0.f, 0.f, 0.f, 0.f);
            const int j1 = s_rp[n + 1];
            for (int j = s_rp[n]; j < j1; j++) {
                int2  ed = s_edge[j];
                float wt = __int_as_float(ed.y);
                float4 xv = xt4[ed.x * PAD_ + p];
                a.x += wt * xv.x; a.y += wt * xv.y;
                a.z += wt * xv.z; a.w += wt * xv.w;
            }
            aggs4[n * PAD_ + p] = a;
        }
    }
    __syncwarp();   // warp w consumes only its own nodes below

    // ---- P5: composed 4->32 transform + gated activation, acc over p ----
    float wz[F_], wh[F_];
    #pragma unroll
    for (int f = 0; f < F_; f++) { wz[f] = s_wz[f * EMB_ + lane]; wh[f] = s_wh[f * EMB_ + lane]; }
    const float bzr = s_bz[lane], bhr = s_bh[lane];

    float acc[7];
    #pragma unroll
    for (int k = 0; k < 7; k++) acc[k] = 0.f;

    for (int p = 0; p < pc; p++) {
        const float pr2 = s_probs[p];     // = 0.5 * softmax prob
        #pragma unroll
        for (int k = 0; k < 7; k++) {
            int n = w + 8 * k;
            if (n >= N_) break;
            float4 a = aggs4[n * PAD_ + p];
            float zh = bzr + a.x * wz[0] + a.y * wz[1] + a.z * wz[2] + a.w * wz[3]; // za/2
            float ha = bhr + a.x * wh[0] + a.y * wh[1] + a.z * wh[2] + a.w * wh[3];
            float t1 = htanh(zh);
            float t2 = htanh(ha);
            // pr*(1-sigmoid(za))*tanh(ha) = (pr2 - pr2*t1) * t2
            float tmp = fmaf(t1, -pr2, pr2);
            acc[k] = fmaf(tmp, t2, acc[k]);
        }
    }

    float* op = g_part + (size_t)(c * B_ + b) * ROW_;
    #pragma unroll
    for (int k = 0; k < 7; k++) {
        int i = tid + 256 * k;
        if (i < ROW_) op[i] = acc[k];
    }

    // ---- Tail: last-arriving block for this b runs the MLP head ----
    __threadfence();
    if (tid == 0) {
        int old = atomicAdd(&g_count[b], 1);
        s_last = (old == CH_ - 1) ? 1 : 0;
    }
    __syncthreads();
    if (!s_last) return;
    __threadfence();

    float* sh = (float*)aggs4;   // 1632 floats
    float* w1 = (float*)xt4;     // 1024 floats

    for (int i = tid; i < ROW_ / 4; i += 256) {
        const float4* gp = (const float4*)(g_part + (size_t)b * ROW_) + i;
        const size_t stride4 = (size_t)B_ * ROW_ / 4;
        float4 s = make_float4(0.f, 0.f, 0.f, 0.f);
        #pragma unroll
        for (int cc = 0; cc < CH_; cc++) {
            float4 v = gp[cc * stride4];
            s.x += v.x; s.y += v.y; s.z += v.z; s.w += v.w;
        }
        ((float4*)sh)[i] = make_float4(fmaxf(s.x, 0.f), fmaxf(s.y, 0.f),
                                       fmaxf(s.z, 0.f), fmaxf(s.w, 0.f));
    }
    for (int i = tid; i < EMB_ * 32; i += 256) w1[i] = l1w[i];
    __syncthreads();

    const float w2j = l2w[lane];
    const float b1j = l1b[lane];
    for (int idx = tid; idx < N_ * 32; idx += 256) {
        int n = idx >> 5;                  // idx&31 == lane
        float a = b1j;
        #pragma unroll
        for (int e = 0; e < EMB_; e++) a += sh[n * EMB_ + e] * w1[e * 32 + lane];
        a = fmaxf(a, 0.f) * w2j;
        #pragma unroll
        for (int o = 16; o; o >>= 1) a += __shfl_xor_sync(0xffffffffu, a, o);
        if (lane == 0) s_ssum[n] = a;
    }
    __syncthreads();

    if (tid < 32) {
        float v = 0.f;
        const float b2 = l2b[0];
        for (int n = lane; n < N_; n += 32) v += (s_ssum[n] + b2) * l3w[n];
        #pragma unroll
        for (int o = 16; o; o >>= 1) v += __shfl_xor_sync(0xffffffffu, v, o);
        if (lane == 0) {
            out[b] = 1.f / (1.f + __expf(-(v + l3b[0])));
            g_count[b] = 0;                // reset for next graph replay
        }
    }
}

// ---------------------------------------------------------------------------
extern "C" void kernel_launch(void* const* d_in, const int* in_sizes, int n_in,
                              void* d_out, int out_size) {
    const float* x   = (const float*)d_in[0];
    const int*   ei  = (const int*)  d_in[1];
    const float* czw = (const float*)d_in[2];
    const float* czb = (const float*)d_in[3];
    // d_in[4..5]: conv_r_* unused (R gate multiplies H == 0)
    const float* chw = (const float*)d_in[6];
    const float* chb = (const float*)d_in[7];
    const float* lzw = (const float*)d_in[8];
    const float* lzb = (const float*)d_in[9];
    // d_in[10..11]: lin_r_* unused
    const float* lhw = (const float*)d_in[12];
    const float* lhb = (const float*)d_in[13];
    const float* att = (const float*)d_in[14];
    const float* l1w = (const float*)d_in[15];
    const float* l1b = (const float*)d_in[16];
    const float* l2w = (const float*)d_in[17];
    const float* l2b = (const float*)d_in[18];
    const float* l3w = (const float*)d_in[19];
    const float* l3b = (const float*)d_in[20];
    float* out = (float*)d_out;

    main_kernel<<<B_ * CH_, 256>>>(x, ei, czw, czb, chw, chb, lzw, lzb, lhw, lhb,
                                   att, l1w, l1b, l2w, l2b, l3w, l3b, out);
}

// round 10
// speedup vs baseline: 1.0625x; 1.0625x over previous
#include <cuda_runtime.h>
#include <math.h>

#define B_    32
#define N_    51
#define F_    4
#define P_    137
#define E_    408
#define NE_   (E_ + N_)      // 459 edges incl self-loops
#define EMB_  32
#define NF_   (N_ * F_)      // 204
#define ROW_  (N_ * EMB_)    // 1632
#define CH_   9              // P chunks
#define PC_   16             // p per chunk (last chunk: 9)
#define PAD_  (PC_ + 1)      // 17

// Static device scratch
__device__ float g_part[(size_t)CH_ * B_ * ROW_];   // 2.09 MB partial accumulators
__device__ int   g_count[B_];                        // zero-init; reset each replay

__device__ __forceinline__ float htanh(float x) {
    float r;
    asm("tanh.approx.f32 %0, %1;" : "=f"(r) : "f"(x));
    return r;
}

// ---------------------------------------------------------------------------
// Single fused kernel, 512 threads. Block = (b, p-chunk of 16). Warp-parallel
// setup, warp-private aggregation + transform, last block per b runs MLP head.
// ---------------------------------------------------------------------------
__global__ __launch_bounds__(512, 2) void main_kernel(
    const float* __restrict__ x,   const int* __restrict__ ei,
    const float* __restrict__ czw, const float* __restrict__ czb,
    const float* __restrict__ chw, const float* __restrict__ chb,
    const float* __restrict__ lzw, const float* __restrict__ lzb,
    const float* __restrict__ lhw, const float* __restrict__ lhb,
    const float* __restrict__ att,
    const float* __restrict__ l1w, const float* __restrict__ l1b,
    const float* __restrict__ l2w, const float* __restrict__ l2b,
    const float* __restrict__ l3w, const float* __restrict__ l3b,
    float* __restrict__ out)
{
    __shared__ float4 xt4  [N_ * PAD_];   // [n][p] over 4 f-channels
    __shared__ float4 aggs4[N_ * PAD_];
    __shared__ int    s_src[E_], s_dst[E_];
    __shared__ int2   s_edge[NE_];        // {src, nrm bits}
    __shared__ int    s_deg[N_], s_cnt[N_];
    __shared__ float  s_dinv[N_];
    __shared__ int    s_rp[N_ + 1];
    __shared__ float  s_wz[F_ * EMB_], s_wh[F_ * EMB_];
    __shared__ float  s_bz[EMB_], s_bh[EMB_];
    __shared__ float  s_probs[PC_];       // pre-scaled by 0.5
    __shared__ float  s_ssum[N_ + 1];
    __shared__ int    s_last;

    const int tid = threadIdx.x, lane = tid & 31, w = tid >> 5;   // 16 warps
    const int c  = blockIdx.x % CH_;
    const int b  = blockIdx.x / CH_;
    const int p0 = c * PC_;
    const int pc = min(PC_, P_ - p0);     // 16, or 9 for c == 8

    // ---- P0: warps 0-7: edges + x tile; warps 8-15: weight composition ----
    if (tid < 256) {
        if (tid < N_) s_deg[tid] = 0;
        for (int i = tid; i < E_; i += 256) { s_src[i] = ei[i]; s_dst[i] = ei[E_ + i]; }
        const float* xb = x + (size_t)b * NF_ * P_ + p0;
        for (int i = tid; i < NF_ * PC_; i += 256) {
            int r = i >> 4, p = i & 15;
            if (p < pc) {
                int n = r >> 2, f = r & 3;
                ((float*)&xt4[n * PAD_ + p])[f] = xb[r * P_ + p];
            }
        }
    } else if (tid < 384) {
        int t = tid - 256, f = t >> 5, e = t & 31;
        float a = 0.f;
        #pragma unroll
        for (int k = 0; k < EMB_; k++) a += czw[f * EMB_ + k] * lzw[k * EMB_ + e];
        s_wz[t] = a * 0.5f;               // tanh half-arg form
        if (f == 0) {
            float bb = lzb[e];
            #pragma unroll
            for (int k = 0; k < EMB_; k++) bb += czb[k] * lzw[k * EMB_ + e];
            s_bz[e] = bb * 0.5f;
        }
    } else {
        int t = tid - 384, f = t >> 5, e = t & 31;
        float a = 0.f;
        #pragma unroll
        for (int k = 0; k < EMB_; k++) a += chw[f * EMB_ + k] * lhw[k * EMB_ + e];
        s_wh[t] = a;
        if (f == 0) {
            float bb = lhb[e];
            #pragma unroll
            for (int k = 0; k < EMB_; k++) bb += chb[k] * lhw[k * EMB_ + e];
            s_bh[e] = bb;
        }
    }
    __syncthreads();

    // ---- P1: degrees (int smem atomics -> deterministic) ----
    if (tid < E_) atomicAdd(&s_deg[s_dst[tid]], 1);
    __syncthreads();

    // ---- P2: scan (warp 0) | softmax (warp 1) | dinv | zero counters ----
    if (w == 0) {
        int v = (lane < N_) ? s_deg[lane] + 1 : 0;
        #pragma unroll
        for (int o = 1; o < 32; o <<= 1) {
            int t = __shfl_up_sync(0xffffffffu, v, o);
            if (lane >= o) v += t;
        }
        int base = __shfl_sync(0xffffffffu, v, 31);
        int v2 = (lane < N_ - 32) ? s_deg[32 + lane] + 1 : 0;
        #pragma unroll
        for (int o = 1; o < 32; o <<= 1) {
            int t = __shfl_up_sync(0xffffffffu, v2, o);
            if (lane >= o) v2 += t;
        }
        if (lane == 0) s_rp[0] = 0;
        s_rp[lane + 1] = v;
        if (lane < N_ - 32) s_rp[33 + lane] = base + v2;
    } else if (w == 1) {
        float mx = -1e30f;
        for (int p = lane; p < P_; p += 32) mx = fmaxf(mx, att[p]);
        #pragma unroll
        for (int o = 16; o; o >>= 1) mx = fmaxf(mx, __shfl_xor_sync(0xffffffffu, mx, o));
        float s = 0.f;
        for (int p = lane; p < P_; p += 32) s += __expf(att[p] - mx);
        #pragma unroll
        for (int o = 16; o; o >>= 1) s += __shfl_xor_sync(0xffffffffu, s, o);
        float inv = 0.5f / s;             // fold the 0.5 gate factor here
        if (lane < pc) s_probs[lane] = __expf(att[p0 + lane] - mx) * inv;
    } else if (tid >= 64 && tid < 64 + N_) {
        s_dinv[tid - 64] = rsqrtf((float)(s_deg[tid - 64] + 1));
    } else if (tid >= 128 && tid < 128 + N_) {
        s_cnt[tid - 128] = 0;
    }
    __syncthreads();

    // ---- P3: CSR fill via match_any tiles (warp 0) | self loops (others) ----
    if (w == 0) {
        #pragma unroll 1
        for (int t = 0; t < (E_ + 31) / 32; t++) {
            int e = t * 32 + lane;
            bool valid = e < E_;
            int d = valid ? s_dst[e] : -1;
            unsigned grp = __match_any_sync(0xffffffffu, d);
            int within = __popc(grp & ((1u << lane) - 1u));
            int lead   = __ffs(grp) - 1;
            int base = 0;
            if (valid) {
                base = s_cnt[d];
                int pos = s_rp[d] + base + within;
                int s   = s_src[e];
                s_edge[pos] = make_int2(s, __float_as_int(s_dinv[s] * s_dinv[d]));
            }
            __syncwarp();
            if (valid && lane == lead) s_cnt[d] = base + __popc(grp);
            __syncwarp();
        }
    } else if (tid >= 32 && tid < 32 + N_) {
        int n = tid - 32;
        int pos = s_rp[n + 1] - 1;        // self loop in last slot
        float dn = s_dinv[n];
        s_edge[pos] = make_int2(n, __float_as_int(dn * dn));
    }
    __syncthreads();

    // ---- P4: WARP-PRIVATE aggregation: warp w handles nodes w, w+16, ... ----
    {
        int nn = (w + 48 < N_) ? 4 : 3;   // warps 0-2 own a 4th node
        for (int i = lane; i < nn * PC_; i += 32) {
            int nl = i >> 4, p = i & 15;
            int n = w + 16 * nl;
            if (p < pc) {
                float4 a = make_float4(0.f, 0.f, 0.f, 0.f);
                const int j1 = s_rp[n + 1];
                for (int j = s_rp[n]; j < j1; j++) {
                    int2  ed = s_edge[j];
                    float wt = __int_as_float(ed.y);
                    float4 xv = xt4[ed.x * PAD_ + p];
                    a.x += wt * xv.x; a.y += wt * xv.y;
                    a.z += wt * xv.z; a.w += wt * xv.w;
                }
                aggs4[n * PAD_ + p] = a;
            }
        }
    }
    __syncwarp();   // warp w consumes only its own nodes below

    // ---- P5: composed 4->32 transform + gated activation, acc over p ----
    float wz[F_], wh[F_];
    #pragma unroll
    for (int f = 0; f < F_; f++) { wz[f] = s_wz[f * EMB_ + lane]; wh[f] = s_wh[f * EMB_ + lane]; }
    const float bzr = s_bz[lane], bhr = s_bh[lane];

    float acc[4] = {0.f, 0.f, 0.f, 0.f};

    #define P5_BODY(p)                                                          \
        {                                                                       \
            const float pr2 = s_probs[p];                                       \
            _Pragma("unroll")                                                   \
            for (int k = 0; k < 4; k++) {                                       \
                int n = w + 16 * k;                                             \
                if (n < N_) {                                                   \
                    float4 a = aggs4[n * PAD_ + (p)];                           \
                    float zh = bzr + a.x*wz[0] + a.y*wz[1] + a.z*wz[2] + a.w*wz[3]; \
                    float ha = bhr + a.x*wh[0] + a.y*wh[1] + a.z*wh[2] + a.w*wh[3]; \
                    float t1 = htanh(zh);                                       \
                    float t2 = htanh(ha);                                       \
                    float tmp = fmaf(t1, -pr2, pr2);                            \
                    acc[k] = fmaf(tmp, t2, acc[k]);                             \
                }                                                               \
            }                                                                   \
        }

    if (pc == PC_) {
        #pragma unroll 4
        for (int p = 0; p < PC_; p++) P5_BODY(p)
    } else {
        for (int p = 0; p < pc; p++) P5_BODY(p)
    }
    #undef P5_BODY

    float* op = g_part + (size_t)(c * B_ + b) * ROW_;
    #pragma unroll
    for (int k = 0; k < 4; k++) {
        int i = tid + 512 * k;            // = (w+16k)*32 + lane = n*32 + e
        if (i < ROW_) op[i] = acc[k];
    }

    // ---- Tail: last-arriving block for this b runs the MLP head ----
    __threadfence();
    if (tid == 0) {
        int old = atomicAdd(&g_count[b], 1);
        s_last = (old == CH_ - 1) ? 1 : 0;
    }
    __syncthreads();
    if (!s_last) return;
    __threadfence();

    float* sh = (float*)aggs4;   // 1632 floats
    float* w1 = (float*)xt4;     // 1024 floats

    if (tid < ROW_ / 4) {
        const float4* gp = (const float4*)(g_part + (size_t)b * ROW_) + tid;
        const size_t stride4 = (size_t)B_ * ROW_ / 4;
        float4 s = make_float4(0.f, 0.f, 0.f, 0.f);
        #pragma unroll
        for (int cc = 0; cc < CH_; cc++) {
            float4 v = gp[cc * stride4];
            s.x += v.x; s.y += v.y; s.z += v.z; s.w += v.w;
        }
        ((float4*)sh)[tid] = make_float4(fmaxf(s.x, 0.f), fmaxf(s.y, 0.f),
                                         fmaxf(s.z, 0.f), fmaxf(s.w, 0.f));
    }
    for (int i = tid; i < EMB_ * 32; i += 512) w1[i] = l1w[i];
    __syncthreads();

    const float w2j = l2w[lane];
    const float b1j = l1b[lane];
    for (int idx = tid; idx < N_ * 32; idx += 512) {
        int n = idx >> 5;                  // idx&31 == lane
        float a = b1j;
        #pragma unroll
        for (int e = 0; e < EMB_; e++) a += sh[n * EMB_ + e] * w1[e * 32 + lane];
        a = fmaxf(a, 0.f) * w2j;
        #pragma unroll
        for (int o = 16; o; o >>= 1) a += __shfl_xor_sync(0xffffffffu, a, o);
        if (lane == 0) s_ssum[n] = a;
    }
    __syncthreads();

    if (tid < 32) {
        float v = 0.f;
        const float b2 = l2b[0];
        for (int n = lane; n < N_; n += 32) v += (s_ssum[n] + b2) * l3w[n];
        #pragma unroll
        for (int o = 16; o; o >>= 1) v += __shfl_xor_sync(0xffffffffu, v, o);
        if (lane == 0) {
            out[b] = 1.f / (1.f + __expf(-(v + l3b[0])));
            g_count[b] = 0;                // reset for next graph replay
        }
    }
}

// ---------------------------------------------------------------------------
extern "C" void kernel_launch(void* const* d_in, const int* in_sizes, int n_in,
                              void* d_out, int out_size) {
    const float* x   = (const float*)d_in[0];
    const int*   ei  = (const int*)  d_in[1];
    const float* czw = (const float*)d_in[2];
    const float* czb = (const float*)d_in[3];
    // d_in[4..5]: conv_r_* unused (R gate multiplies H == 0)
    const float* chw = (const float*)d_in[6];
    const float* chb = (const float*)d_in[7];
    const float* lzw = (const float*)d_in[8];
    const float* lzb = (const float*)d_in[9];
    // d_in[10..11]: lin_r_* unused
    const float* lhw = (const float*)d_in[12];
    const float* lhb = (const float*)d_in[13];
    const float* att = (const float*)d_in[14];
    const float* l1w = (const float*)d_in[15];
    const float* l1b = (const float*)d_in[16];
    const float* l2w = (const float*)d_in[17];
    const float* l2b = (const float*)d_in[18];
    const float* l3w = (const float*)d_in[19];
    const float* l3b = (const float*)d_in[20];
    float* out = (float*)d_out;

    main_kernel<<<B_ * CH_, 512>>>(x, ei, czw, czb, chw, chb, lzw, lzb, lhw, lhb,
                                   att, l1w, l1b, l2w, l2b, l3w, l3b, out);
}

// round 11
// speedup vs baseline: 1.1586x; 1.0904x over previous
#include <cuda_runtime.h>
#include <math.h>

#define B_    32
#define N_    51
#define F_    4
#define P_    137
#define E_    408
#define NE_   (E_ + N_)      // 459 edges incl self-loops
#define EMB_  32
#define NF_   (N_ * F_)      // 204
#define ROW_  (N_ * EMB_)    // 1632
#define CH_   9              // P chunks
#define PC_   16             // p per chunk (last chunk: 9)
#define PAD_  (PC_ + 1)      // 17
#define NT_   13             // 32-edge tiles

// Static device scratch
__device__ float g_part[(size_t)CH_ * B_ * ROW_];   // 2.09 MB partial accumulators
__device__ int   g_count[B_];                        // zero-init; reset each replay

typedef unsigned long long ull;

__device__ __forceinline__ float htanh(float x) {
    float r;
    asm("tanh.approx.f32 %0, %1;" : "=f"(r) : "f"(x));
    return r;
}
__device__ __forceinline__ ull pk(float lo, float hi) {
    ull r;
    asm("mov.b64 %0, {%1, %2};" : "=l"(r) : "f"(lo), "f"(hi));
    return r;
}
__device__ __forceinline__ void upk(float& lo, float& hi, ull v) {
    asm("mov.b64 {%0, %1}, %2;" : "=f"(lo), "=f"(hi) : "l"(v));
}
__device__ __forceinline__ ull fma2(ull a, ull b, ull c) {
    ull d;
    asm("fma.rn.f32x2 %0, %1, %2, %3;" : "=l"(d) : "l"(a), "l"(b), "l"(c));
    return d;
}

// ---------------------------------------------------------------------------
// Single fused kernel, 256 threads, grid B*CH. Fully parallel per-block setup
// (no serial CSR chain), FFMA2-packed transform, last block per b runs head.
// ---------------------------------------------------------------------------
__global__ __launch_bounds__(256, 2) void main_kernel(
    const float* __restrict__ x,   const int* __restrict__ ei,
    const float* __restrict__ czw, const float* __restrict__ czb,
    const float* __restrict__ chw, const float* __restrict__ chb,
    const float* __restrict__ lzw, const float* __restrict__ lzb,
    const float* __restrict__ lhw, const float* __restrict__ lhb,
    const float* __restrict__ att,
    const float* __restrict__ l1w, const float* __restrict__ l1b,
    const float* __restrict__ l2w, const float* __restrict__ l2b,
    const float* __restrict__ l3w, const float* __restrict__ l3b,
    float* __restrict__ out)
{
    __shared__ float4 xt4  [N_ * PAD_];   // [n][p] over 4 f-channels
    __shared__ float4 aggs4[N_ * PAD_];
    __shared__ int    s_src[E_], s_dst[E_];
    __shared__ int2   s_edge[NE_];        // {src, nrm bits}
    __shared__ int    s_deg[N_];
    __shared__ int    s_rp[N_ + 1];
    __shared__ int    s_hist[NT_ * N_];   // per-tile per-node edge counts
    __shared__ unsigned char s_rank[E_];  // within-tile rank of each edge
    __shared__ float  s_wz[F_ * EMB_], s_wh[F_ * EMB_];
    __shared__ float  s_bz[EMB_], s_bh[EMB_];
    __shared__ float  s_probs[PC_];       // pre-scaled by 0.5
    __shared__ float  s_ssum[N_ + 1];
    __shared__ int    s_last;

    const int tid = threadIdx.x, lane = tid & 31, w = tid >> 5;   // 8 warps
    const int c  = blockIdx.x % CH_;
    const int b  = blockIdx.x / CH_;
    const int p0 = c * PC_;
    const int pc = min(PC_, P_ - p0);     // 16, or 9 for c == 8

    // ---- P0: edges, hist zero, x tile, composed weights (independent) ----
    if (tid < N_) s_deg[tid] = 0;
    for (int i = tid; i < NT_ * N_; i += 256) s_hist[i] = 0;
    for (int i = tid; i < E_; i += 256) { s_src[i] = ei[i]; s_dst[i] = ei[E_ + i]; }

    const float* xb = x + (size_t)b * NF_ * P_ + p0;
    for (int r = w; r < NF_; r += 8) {
        int n = r >> 2, f = r & 3;
        if (lane < pc)
            ((float*)&xt4[n * PAD_ + lane])[f] = xb[r * P_ + lane];
    }

    // composed weights: wz' = 0.5*(czw@lzw) (tanh half-arg), wh' = chw@lhw
    if (tid < 128) {
        int f = tid >> 5, e = tid & 31;
        float a = 0.f;
        #pragma unroll
        for (int k = 0; k < EMB_; k++) a += czw[f * EMB_ + k] * lzw[k * EMB_ + e];
        s_wz[tid] = a * 0.5f;
        if (f == 0) {
            float bb = lzb[e];
            #pragma unroll
            for (int k = 0; k < EMB_; k++) bb += czb[k] * lzw[k * EMB_ + e];
            s_bz[e] = bb * 0.5f;
        }
    } else {
        int t = tid - 128, f = t >> 5, e = t & 31;
        float a = 0.f;
        #pragma unroll
        for (int k = 0; k < EMB_; k++) a += chw[f * EMB_ + k] * lhw[k * EMB_ + e];
        s_wh[t] = a;
        if (f == 0) {
            float bb = lhb[e];
            #pragma unroll
            for (int k = 0; k < EMB_; k++) bb += chb[k] * lhw[k * EMB_ + e];
            s_bh[e] = bb;
        }
    }
    __syncthreads();

    // ---- P1: degrees (int smem atomics -> deterministic) ----
    for (int e = tid; e < E_; e += 256) atomicAdd(&s_deg[s_dst[e]], 1);
    __syncthreads();

    // ---- P2: scan (w0) | softmax (w1) | tile hist + ranks (w2-7, parallel) ----
    if (w == 0) {
        int v = (lane < N_) ? s_deg[lane] + 1 : 0;
        #pragma unroll
        for (int o = 1; o < 32; o <<= 1) {
            int t = __shfl_up_sync(0xffffffffu, v, o);
            if (lane >= o) v += t;
        }
        int base = __shfl_sync(0xffffffffu, v, 31);
        int v2 = (lane < N_ - 32) ? s_deg[32 + lane] + 1 : 0;
        #pragma unroll
        for (int o = 1; o < 32; o <<= 1) {
            int t = __shfl_up_sync(0xffffffffu, v2, o);
            if (lane >= o) v2 += t;
        }
        if (lane == 0) s_rp[0] = 0;
        s_rp[lane + 1] = v;
        if (lane < N_ - 32) s_rp[33 + lane] = base + v2;
    } else if (w == 1) {
        float mx = -1e30f;
        for (int p = lane; p < P_; p += 32) mx = fmaxf(mx, att[p]);
        #pragma unroll
        for (int o = 16; o; o >>= 1) mx = fmaxf(mx, __shfl_xor_sync(0xffffffffu, mx, o));
        float s = 0.f;
        for (int p = lane; p < P_; p += 32) s += __expf(att[p] - mx);
        #pragma unroll
        for (int o = 16; o; o >>= 1) s += __shfl_xor_sync(0xffffffffu, s, o);
        float inv = 0.5f / s;             // fold the 0.5 gate factor here
        if (lane < pc) s_probs[lane] = __expf(att[p0 + lane] - mx) * inv;
    } else {
        // warps 2..7: independent 32-edge tiles (no cross-tile dependency)
        for (int t = w - 2; t < NT_; t += 6) {
            int e = t * 32 + lane;
            bool valid = e < E_;
            int d = valid ? s_dst[e] : -1;
            unsigned grp = __match_any_sync(0xffffffffu, d);
            if (valid) {
                int within = __popc(grp & ((1u << lane) - 1u));
                s_rank[e] = (unsigned char)within;
                if (within == 0) s_hist[t * N_ + d] = __popc(grp);
            }
        }
    }
    __syncthreads();

    // ---- P3: edge-parallel slot write + self loops ----
    for (int i = tid; i < NE_; i += 256) {
        if (i < E_) {
            int d = s_dst[i], s = s_src[i];
            int t = i >> 5;
            int base = s_rp[d] + (int)s_rank[i];
            for (int tt = 0; tt < t; tt++) base += s_hist[tt * N_ + d];
            float nrm = rsqrtf((float)(s_deg[s] + 1)) * rsqrtf((float)(s_deg[d] + 1));
            s_edge[base] = make_int2(s, __float_as_int(nrm));
        } else {
            int n = i - E_;
            float dn = rsqrtf((float)(s_deg[n] + 1));
            s_edge[s_rp[n + 1] - 1] = make_int2(n, __float_as_int(dn * dn));
        }
    }
    __syncthreads();

    // ---- P4: WARP-PRIVATE aggregation: warp w handles nodes w, w+8, ... ----
    for (int i = lane; i < 7 * PC_; i += 32) {
        int nl = i >> 4, p = i & 15;
        int n = w + 8 * nl;
        if (n < N_ && p < pc) {
            float4 a = make_float4(0.f, 0.f, 0.f, 0.f);
            const int j1 = s_rp[n + 1];
            for (int j = s_rp[n]; j < j1; j++) {
                int2  ed = s_edge[j];
                float wt = __int_as_float(ed.y);
                float4 xv = xt4[ed.x * PAD_ + p];
                a.x += wt * xv.x; a.y += wt * xv.y;
                a.z += wt * xv.z; a.w += wt * xv.w;
            }
            aggs4[n * PAD_ + p] = a;
        }
    }
    __syncwarp();   // warp w consumes only its own nodes below

    // ---- P5: FFMA2-packed 4->32 transform + gated activation over p-pairs ----
    ull wz2[F_], wh2[F_];
    #pragma unroll
    for (int f = 0; f < F_; f++) {
        float vz = s_wz[f * EMB_ + lane], vh = s_wh[f * EMB_ + lane];
        wz2[f] = pk(vz, vz); wh2[f] = pk(vh, vh);
    }
    const float bzr = s_bz[lane], bhr = s_bh[lane];
    const ull bz2 = pk(bzr, bzr), bh2 = pk(bhr, bhr);

    ull  acc2[7];
    #pragma unroll
    for (int k = 0; k < 7; k++) acc2[k] = pk(0.f, 0.f);
    float accT[7] = {0.f, 0.f, 0.f, 0.f, 0.f, 0.f, 0.f};

    const int qmax = pc >> 1;
    for (int q = 0; q < qmax; q++) {
        const int pA = 2 * q, pB = 2 * q + 1;
        const float prl = s_probs[pA], prh = s_probs[pB];
        const ull pr2  = pk(prl, prh);
        const ull npr2 = pk(-prl, -prh);
        #pragma unroll
        for (int k = 0; k < 7; k++) {
            int n = w + 8 * k;
            if (n >= N_) break;
            float4 a0 = aggs4[n * PAD_ + pA];
            float4 a1 = aggs4[n * PAD_ + pB];
            ull ax = pk(a0.x, a1.x), ay = pk(a0.y, a1.y);
            ull az = pk(a0.z, a1.z), aw = pk(a0.w, a1.w);
            ull zh = fma2(ax, wz2[0], bz2);
            zh = fma2(ay, wz2[1], zh); zh = fma2(az, wz2[2], zh); zh = fma2(aw, wz2[3], zh);
            ull hh = fma2(ax, wh2[0], bh2);
            hh = fma2(ay, wh2[1], hh); hh = fma2(az, wh2[2], hh); hh = fma2(aw, wh2[3], hh);
            float z0, z1, h0, h1;
            upk(z0, z1, zh); upk(h0, h1, hh);
            ull t1 = pk(htanh(z0), htanh(z1));
            ull t2 = pk(htanh(h0), htanh(h1));
            ull tmp = fma2(t1, npr2, pr2);      // (pr2 - pr2*t1) per half
            acc2[k] = fma2(tmp, t2, acc2[k]);
        }
    }
    if (pc & 1) {
        const int p = pc - 1;
        const float pr2 = s_probs[p];
        #pragma unroll
        for (int k = 0; k < 7; k++) {
            int n = w + 8 * k;
            if (n >= N_) break;
            float4 a = aggs4[n * PAD_ + p];
            float zh = bzr + a.x * __int_as_float(__float_as_int(0)) ; // placeholder avoided below
            zh = bzr; float ha = bhr;
            zh += a.x * s_wz[0 * EMB_ + lane] + a.y * s_wz[1 * EMB_ + lane]
                + a.z * s_wz[2 * EMB_ + lane] + a.w * s_wz[3 * EMB_ + lane];
            ha += a.x * s_wh[0 * EMB_ + lane] + a.y * s_wh[1 * EMB_ + lane]
                + a.z * s_wh[2 * EMB_ + lane] + a.w * s_wh[3 * EMB_ + lane];
            float t1 = htanh(zh);
            float t2 = htanh(ha);
            float tmp = fmaf(t1, -pr2, pr2);
            accT[k] = fmaf(tmp, t2, accT[k]);
        }
    }

    float* op = g_part + (size_t)(c * B_ + b) * ROW_;
    #pragma unroll
    for (int k = 0; k < 7; k++) {
        int i = tid + 256 * k;                // = (w+8k)*32 + lane
        if (i < ROW_) {
            float lo, hi;
            upk(lo, hi, acc2[k]);
            op[i] = lo + hi + accT[k];
        }
    }

    // ---- Tail: last-arriving block for this b runs the MLP head ----
    __threadfence();
    if (tid == 0) {
        int old = atomicAdd(&g_count[b], 1);
        s_last = (old == CH_ - 1) ? 1 : 0;
    }
    __syncthreads();
    if (!s_last) return;
    __threadfence();

    float* sh = (float*)aggs4;   // 1632 floats
    float* w1 = (float*)xt4;     // 1024 floats

    for (int i = tid; i < ROW_ / 4; i += 256) {
        const float4* gp = (const float4*)(g_part + (size_t)b * ROW_) + i;
        const size_t stride4 = (size_t)B_ * ROW_ / 4;
        float4 s = make_float4(0.f, 0.f, 0.f, 0.f);
        #pragma unroll
        for (int cc = 0; cc < CH_; cc++) {
            float4 v = gp[cc * stride4];
            s.x += v.x; s.y += v.y; s.z += v.z; s.w += v.w;
        }
        ((float4*)sh)[i] = make_float4(fmaxf(s.x, 0.f), fmaxf(s.y, 0.f),
                                       fmaxf(s.z, 0.f), fmaxf(s.w, 0.f));
    }
    for (int i = tid; i < EMB_ * 32; i += 256) w1[i] = l1w[i];
    __syncthreads();

    const float w2j = l2w[lane];
    const float b1j = l1b[lane];
    for (int idx = tid; idx < N_ * 32; idx += 256) {
        int n = idx >> 5;                  // idx&31 == lane
        float a = b1j;
        #pragma unroll
        for (int e = 0; e < EMB_; e++) a += sh[n * EMB_ + e] * w1[e * 32 + lane];
        a = fmaxf(a, 0.f) * w2j;
        #pragma unroll
        for (int o = 16; o; o >>= 1) a += __shfl_xor_sync(0xffffffffu, a, o);
        if (lane == 0) s_ssum[n] = a;
    }
    __syncthreads();

    if (tid < 32) {
        float v = 0.f;
        const float b2 = l2b[0];
        for (int n = lane; n < N_; n += 32) v += (s_ssum[n] + b2) * l3w[n];
        #pragma unroll
        for (int o = 16; o; o >>= 1) v += __shfl_xor_sync(0xffffffffu, v, o);
        if (lane == 0) {
            out[b] = 1.f / (1.f + __expf(-(v + l3b[0])));
            g_count[b] = 0;                // reset for next graph replay
        }
    }
}

// ---------------------------------------------------------------------------
extern "C" void kernel_launch(void* const* d_in, const int* in_sizes, int n_in,
                              void* d_out, int out_size) {
    const float* x   = (const float*)d_in[0];
    const int*   ei  = (const int*)  d_in[1];
    const float* czw = (const float*)d_in[2];
    const float* czb = (const float*)d_in[3];
    // d_in[4..5]: conv_r_* unused (R gate multiplies H == 0)
    const float* chw = (const float*)d_in[6];
    const float* chb = (const float*)d_in[7];
    const float* lzw = (const float*)d_in[8];
    const float* lzb = (const float*)d_in[9];
    // d_in[10..11]: lin_r_* unused
    const float* lhw = (const float*)d_in[12];
    const float* lhb = (const float*)d_in[13];
    const float* att = (const float*)d_in[14];
    const float* l1w = (const float*)d_in[15];
    const float* l1b = (const float*)d_in[16];
    const float* l2w = (const float*)d_in[17];
    const float* l2b = (const float*)d_in[18];
    const float* l3w = (const float*)d_in[19];
    const float* l3b = (const float*)d_in[20];
    float* out = (float*)d_out;

    main_kernel<<<B_ * CH_, 256>>>(x, ei, czw, czb, chw, chb, lzw, lzb, lhw, lhb,
                                   att, l1w, l1b, l2w, l2b, l3w, l3b, out);
}